// round 12
// baseline (speedup 1.0000x reference)
#include <cuda_runtime.h>
#include <cuda_bf16.h>
#include <cstdint>

// SudokuDigitsDoubles — exact boolean reduction ("naked pairs" row elimination).
//
// Round 12: R11's persistent double-buffered cp.async.bulk pipeline with
// 2x larger tiles (PPB=16 -> 46656B per bulk transfer) to halve HBM
// read<->write turnaround frequency. Requires dynamic smem (93.4KB) via
// cudaFuncSetAttribute (idempotent, capture-safe, no allocation).
// Bench time is pinned at total-DRAM-traffic / mixed-stream BW; this round
// attacks the mixed-stream BW term.

static constexpr int PUZ = 729;                   // floats per puzzle
static constexpr int PPB = 16;                    // puzzles per tile
static constexpr int NF  = PPB * PUZ;             // 11664 floats per tile
static constexpr unsigned TILE_BYTES = NF * 4;    // 46656
static constexpr int THREADS = 256;
static constexpr int GRID_CTAS = 296;             // 2 per SM * 148 SMs
// dynamic smem: 2 tiles + barriers + alignment slack
static constexpr unsigned SMEM_BYTES = 2 * TILE_BYTES + 256;

__device__ __forceinline__ unsigned smem_u32(const void* p) {
    unsigned a;
    asm("{ .reg .u64 t; cvta.to.shared.u64 t, %1; cvt.u32.u64 %0, t; }"
        : "=r"(a) : "l"(p));
    return a;
}

__device__ __forceinline__ void mbar_wait(unsigned bar, unsigned parity) {
    unsigned done;
    do {
        asm volatile(
            "{\n\t.reg .pred p;\n\t"
            "mbarrier.try_wait.parity.acquire.cta.shared::cta.b64 p, [%1], %2;\n\t"
            "selp.b32 %0, 1, 0, p;\n\t}"
            : "=r"(done) : "r"(bar), "r"(parity) : "memory");
    } while (!done);
}

__device__ __forceinline__ void bulk_load(unsigned dst, const float* src,
                                          unsigned bar, unsigned long long pol) {
    asm volatile("mbarrier.arrive.expect_tx.shared.b64 _, [%0], %1;"
                 :: "r"(bar), "r"(TILE_BYTES) : "memory");
    asm volatile(
        "cp.async.bulk.shared::cluster.global.mbarrier::complete_tx::bytes"
        ".L2::cache_hint [%0], [%1], %2, [%3], %4;"
        :: "r"(dst), "l"(src), "r"(TILE_BYTES), "r"(bar), "l"(pol) : "memory");
}

__global__ __launch_bounds__(THREADS, 2)
void sudoku_doubles_kernel(const float* __restrict__ in,
                           float* __restrict__ out,
                           int nPuz, int nTiles)
{
    extern __shared__ char smraw[];
    // 128B-align the tile region
    uintptr_t base = (uintptr_t)smraw;
    base = (base + 127) & ~(uintptr_t)127;
    float* buf0 = reinterpret_cast<float*>(base);
    float* buf1 = buf0 + NF;
    unsigned long long* mbar = reinterpret_cast<unsigned long long*>(buf1 + NF);
    float* bufs[2] = { buf0, buf1 };

    const unsigned tid = threadIdx.x;
    const unsigned sBar[2] = { smem_u32(&mbar[0]), smem_u32(&mbar[1]) };
    const unsigned sBuf[2] = { smem_u32(buf0), smem_u32(buf1) };

    unsigned long long polLast, polFirst;
    asm("createpolicy.fractional.L2::evict_last.b64 %0, 1.0;"  : "=l"(polLast));
    asm("createpolicy.fractional.L2::evict_first.b64 %0, 1.0;" : "=l"(polFirst));

    if (tid == 0) {
        asm volatile("mbarrier.init.shared.b64 [%0], 1;" :: "r"(sBar[0]) : "memory");
        asm volatile("mbarrier.init.shared.b64 [%0], 1;" :: "r"(sBar[1]) : "memory");
    }
    __syncthreads();

    int ph[2] = {0, 0};
    int b = 0;

    // prologue: first tile's load
    {
        const int tile = blockIdx.x;
        if (tid == 0 && tile < nTiles) {
            const int tb = tile * PPB;
            if (tb + PPB <= nPuz)
                bulk_load(sBuf[0], in + (size_t)tb * PUZ, sBar[0], polLast);
        }
    }

    for (int tile = blockIdx.x; tile < nTiles; tile += gridDim.x, b ^= 1) {
        const int tileBase = tile * PPB;
        const bool full = (tileBase + PPB <= nPuz);

        // ---- prefetch next tile into the other buffer ----
        const int nextTile = tile + gridDim.x;
        if (tid == 0 && nextTile < nTiles) {
            const int ntb = nextTile * PPB;
            if (ntb + PPB <= nPuz) {
                asm volatile("cp.async.bulk.wait_group.read 0;" ::: "memory");
                bulk_load(sBuf[b ^ 1], in + (size_t)ntb * PUZ, sBar[b ^ 1], polLast);
            }
        }

        if (full) {
            mbar_wait(sBar[b], (unsigned)ph[b]);
            ph[b] ^= 1;

            // ---- 144 row leaders: logic directly on the smem tile ----
            if (tid < PPB * 9) {
                const int pl = tid / 9;
                const int r  = tid - 9 * pl;
                const unsigned* rowp =
                    reinterpret_cast<const unsigned*>(bufs[b]) + pl * PUZ + r * 9;

                int m[9], pv[9];
                #pragma unroll
                for (int c = 0; c < 9; c++) {
                    unsigned mm = 0;
                    #pragma unroll
                    for (int d = 0; d < 9; d++)
                        mm |= ((rowp[d * 81 + c] >> 23) & 1u) << d;  // 1.0f vs 0.0f
                    m[c]  = (int)mm;
                    pv[c] = (__popc(mm) == 2) ? m[c] : 0;
                }
                int act = 0, tor = 0;
                #pragma unroll
                for (int j = 0; j < 9; j++) {
                    int cc = 0;
                    #pragma unroll
                    for (int k = 0; k < 9; k++)
                        cc += (pv[k] == pv[j]) ? 1 : 0;
                    const bool a = (pv[j] != 0) & (cc == 2);
                    act |= a ? (1 << j) : 0;
                    tor |= a ? pv[j] : 0;
                }
                if (act) {   // rare: ~0.5% of rows
                    float* o = bufs[b] + pl * PUZ + r * 9;
                    #pragma unroll
                    for (int c = 0; c < 9; c++) {
                        int erase;
                        if ((act >> c) & 1) {
                            erase = 0;
                            #pragma unroll
                            for (int j = 0; j < 9; j++)
                                if (((act >> j) & 1) && pv[j] != pv[c])
                                    erase |= pv[j];
                        } else {
                            erase = tor;
                        }
                        const int keep = m[c] & ~erase;
                        #pragma unroll
                        for (int d = 0; d < 9; d++)
                            o[d * 81 + c] = ((keep >> d) & 1) ? 1.0f : 0.0f;
                    }
                }
            }
            __syncthreads();

            // ---- bulk store this tile ----
            if (tid == 0) {
                asm volatile("fence.proxy.async.shared::cta;" ::: "memory");
                asm volatile(
                    "cp.async.bulk.global.shared::cta.bulk_group"
                    ".L2::cache_hint [%0], [%1], %2, %3;"
                    :: "l"(out + (size_t)tileBase * PUZ), "r"(sBuf[b]),
                       "r"(TILE_BYTES), "l"(polFirst) : "memory");
                asm volatile("cp.async.bulk.commit_group;" ::: "memory");
            }
        } else {
            // ---- partial tail tile: direct scalar path (unused for B=32768) ----
            const int puzCount = nPuz - tileBase;
            if (puzCount > 0 && tid < (unsigned)(puzCount * 9)) {
                const int pl = tid / 9;
                const int r  = tid - 9 * pl;
                const float* gi = in  + (size_t)(tileBase + pl) * PUZ + r * 9;
                float*       go = out + (size_t)(tileBase + pl) * PUZ + r * 9;
                int m[9], pv[9];
                #pragma unroll
                for (int c = 0; c < 9; c++) {
                    unsigned mm = 0;
                    #pragma unroll
                    for (int d = 0; d < 9; d++)
                        mm |= ((__float_as_uint(gi[d * 81 + c]) >> 23) & 1u) << d;
                    m[c]  = (int)mm;
                    pv[c] = (__popc(mm) == 2) ? m[c] : 0;
                }
                int act = 0, tor = 0;
                #pragma unroll
                for (int j = 0; j < 9; j++) {
                    int cc = 0;
                    #pragma unroll
                    for (int k = 0; k < 9; k++)
                        cc += (pv[k] == pv[j]) ? 1 : 0;
                    const bool a = (pv[j] != 0) & (cc == 2);
                    act |= a ? (1 << j) : 0;
                    tor |= a ? pv[j] : 0;
                }
                #pragma unroll
                for (int c = 0; c < 9; c++) {
                    int erase;
                    if ((act >> c) & 1) {
                        erase = 0;
                        #pragma unroll
                        for (int j = 0; j < 9; j++)
                            if (((act >> j) & 1) && pv[j] != pv[c])
                                erase |= pv[j];
                    } else {
                        erase = tor;
                    }
                    const int keep = m[c] & ~erase;
                    #pragma unroll
                    for (int d = 0; d < 9; d++)
                        go[d * 81 + c] = ((keep >> d) & 1) ? 1.0f : 0.0f;
                }
            }
        }
    }

    // drain: last store must finish reading smem before the CTA exits
    if (tid == 0)
        asm volatile("cp.async.bulk.wait_group.read 0;" ::: "memory");
}

extern "C" void kernel_launch(void* const* d_in, const int* in_sizes, int n_in,
                              void* d_out, int out_size)
{
    const float* mask = (const float*)d_in[0];
    float* out = (float*)d_out;
    const int nPuz = in_sizes[0] / PUZ;                 // 32768
    const int nTiles = (nPuz + PPB - 1) / PPB;          // 2048
    const int grid = (nTiles < GRID_CTAS) ? nTiles : GRID_CTAS;

    // opt-in to >48KB dynamic smem (idempotent; attribute set, not an
    // allocation; immediate API — safe under graph capture)
    cudaFuncSetAttribute(sudoku_doubles_kernel,
                         cudaFuncAttributeMaxDynamicSharedMemorySize, SMEM_BYTES);

    sudoku_doubles_kernel<<<grid, THREADS, SMEM_BYTES>>>(mask, out, nPuz, nTiles);
}